// round 12
// baseline (speedup 1.0000x reference)
#include <cuda_runtime.h>

// YOLOv2 region loss — CPT=1 (max warp pool for DRAM BW), geometric GT
// prefilter, block-level queue for masked cells (all warps drain in
// parallel), setup loads issued before smem setup to overlap latency.
// B=16, A=5, C=80, H=W=64, N_GT=50, STRIDE=16, THRESH=0.6

#define NA 5
#define NC 80
#define NGT 50
#define HW 4096
#define CH 85
#define BLK 256
#define NBLOCKS 1280     // 327680 / 256
#define FULL 0xffffffffu

__device__ double g_part[NBLOCKS];
__device__ unsigned int g_flag;   // zero-init; last block resets each launch

__global__ __launch_bounds__(BLK, 5) void rl_loss_kernel(
    const float* __restrict__ outp,
    const float* __restrict__ target,
    const float* __restrict__ anchors,
    float* __restrict__ out)
{
    __shared__ float4 s_box[NGT];      // x1,y1,x2,y2
    __shared__ float  s_m3sa[NGT];     // -3 * gt_area  (phase-1 key)
    __shared__ float  s_sa[NGT];       // exact gt_area (phase-2)
    __shared__ float4 s_gt[NGT];       // cx,cy,w,h
    __shared__ float  s_cls[NGT];
    __shared__ double s_red[8];
    __shared__ int    s_cnt[8];
    __shared__ int    s_q[256];        // masked-cell offsets (worst case)
    __shared__ int    s_last;

    const int tid  = threadIdx.x;
    const int lane = tid & 31;
    const int wid  = tid >> 5;

    // block = 256 consecutive cells of one (b,a); warp = half-row (32 cols)
    const int cellblk = blockIdx.x * BLK;
    const int ba      = cellblk >> 12;
    const int b       = ba / NA;
    const int a       = ba - b * NA;
    const int hwbase  = cellblk & (HW - 1);
    const int oA      = tid;                   // cell offset within block

    const float* base = outp + ((size_t)ba * CH) * HW + hwbase;

    // ---- issue setup loads FIRST (overlap DRAM latency with smem GT setup)
    const float t0   = base[oA];
    const float t1   = base[oA + HW];
    const float t2   = base[oA + 2 * HW];
    const float t3   = base[oA + 3 * HW];
    const float conf = base[oA + 4 * HW];

    if (tid < NGT) {
        const float* t = target + ((size_t)b * NGT + tid) * 5;
        float cls = t[0], cx = t[1], cy = t[2], gw = t[3], gh = t[4];
        float x1 = cx - gw * 0.5f, y1 = cy - gh * 0.5f;
        float x2 = cx + gw * 0.5f, y2 = cy + gh * 0.5f;
        float sa = (x2 - x1) * (y2 - y1);
        s_box[tid]  = make_float4(x1, y1, x2, y2);
        s_m3sa[tid] = -3.0f * sa;
        s_sa[tid]   = sa;
        s_gt[tid]   = make_float4(cx, cy, gw, gh);
        s_cls[tid]  = cls;
    }
    __syncthreads();

    const float aw = anchors[2 * a];
    const float ah = anchors[2 * a + 1];

    const int hwc = hwbase + oA;
    const int h = hwc >> 6, w = hwc & 63;
    const float sx = __fdividef(1.0f, 1.0f + __expf(-t0));
    const float sy = __fdividef(1.0f, 1.0f + __expf(-t1));
    const float pxc = (sx + (float)w) * 16.0f;
    const float pyc = (sy + (float)h) * 16.0f;
    const float pw = __expf(t2) * aw;
    const float ph = __expf(t3) * ah;

    const float px1 = pxc - pw * 0.5f, py1 = pyc - ph * 0.5f;
    const float px2 = pxc + pw * 0.5f, py2 = pyc + ph * 0.5f;
    const float paeps = (px2 - px1) * (py2 - py1) + 1e-6f;

    // ---- Per-warp GT prefilter (necessary condition: GT box must contain a
    // pred center of this warp's 512x16px strip; 1px slack >> fp error).
    unsigned f0, f1;
    {
        const float xlo = (float)((oA & 32) << 4) - 1.0f;
        const float xhi = xlo + 514.0f;
        const float ylo = (float)((hwc >> 6) << 4) - 1.0f;
        const float yhi = ylo + 18.0f;
        float4 bx = s_box[lane];
        bool p = (bx.z > xlo) & (bx.x < xhi) & (bx.w > ylo) & (bx.y < yhi);
        f0 = __ballot_sync(FULL, p);
        bool q = false;
        if (lane < NGT - 32) {
            float4 b2 = s_box[lane + 32];
            q = (b2.z > xlo) & (b2.x < xhi) & (b2.w > ylo) & (b2.y < yhi);
        }
        f1 = __ballot_sync(FULL, q);
    }

    // ---- Phase 1 over surviving GTs: iou_n>0.6 <=> 8*I_n-3*Sg_n > 3*(pa+eps)
    float mk = -1e30f;
    #pragma unroll
    for (int word = 0; word < 2; word++) {
        unsigned bb = word ? f1 : f0;
        const int boff = word << 5;
        while (bb) {
            int n = (__ffs(bb) - 1) + boff;
            bb &= bb - 1;
            float4 bx = s_box[n];
            float cw = fminf(bx.z, px2) - fmaxf(bx.x, px1);
            float ch = fminf(bx.w, py2) - fmaxf(bx.y, py1);
            float I  = fmaxf(cw, 0.0f) * fmaxf(ch, 0.0f);
            mk = fmaxf(mk, fmaf(I, 8.0f, s_m3sa[n]));
        }
    }

    const bool msk = (mk > 3.0f * paeps);
    float loss = msk ? 0.0f : conf * conf;

    // ---- Build deterministic block queue of masked cell offsets.
    unsigned q0 = __ballot_sync(FULL, msk);
    if (lane == 0) s_cnt[wid] = __popc(q0);
    __syncthreads();

    int qoff = 0, qn = 0;
    #pragma unroll
    for (int i = 0; i < 8; i++) {
        int ci = s_cnt[i];
        if (i < wid) qoff += ci;
        qn += ci;
    }
    if (msk) s_q[qoff + __popc(q0 & ((1u << lane) - 1))] = oA;
    __syncthreads();

    // ---- Phase 2: all warps drain the queue round-robin. Exact per-cell:
    // argmax over ALL 50 GTs (cross-mul, first-occurrence ties) + coord/conf
    // loss + class logsumexp. Class loads issued BEFORE argmax (overlap).
    for (int e = wid; e < qn; e += 8) {
        const int o = s_q[e];

        // raw logits for this cell (L1/L2 hot; broadcast loads)
        const float u0 = base[o];
        const float u1 = base[o + HW];
        const float u2 = base[o + 2 * HW];
        const float u3 = base[o + 3 * HW];
        const float cf = base[o + 4 * HW];

        // issue class loads now, consume after argmax
        const float* cl = base + o + 5 * HW;
        const float l0 = cl[(size_t)lane * HW];
        const float l1 = cl[(size_t)(lane + 32) * HW];
        const float l2 = (lane < 16) ? cl[(size_t)(lane + 64) * HW] : 0.0f;

        // rebuild pred box (uniform across warp)
        const int hwq = hwbase + o;
        const int hq = hwq >> 6, wq = hwq & 63;
        const float qsx = __fdividef(1.0f, 1.0f + __expf(-u0));
        const float qsy = __fdividef(1.0f, 1.0f + __expf(-u1));
        const float qxc = (qsx + (float)wq) * 16.0f;
        const float qyc = (qsy + (float)hq) * 16.0f;
        const float qpw = __expf(u2) * aw;
        const float qph = __expf(u3) * ah;
        const float qx1 = qxc - qpw * 0.5f, qy1 = qyc - qph * 0.5f;
        const float qx2 = qxc + qpw * 0.5f, qy2 = qyc + qph * 0.5f;
        const float qpa = (qx2 - qx1) * (qy2 - qy1) + 1e-6f;

        // lanes split 50 GTs; cross-multiplied compare (monotone-equiv to
        // iou = I/(S-I)); smaller index wins ties = first-occurrence argmax
        float bI, bS; int bidx;
        {
            float4 bx = s_box[lane];
            float cw = fminf(bx.z, qx2) - fmaxf(bx.x, qx1);
            float ch = fminf(bx.w, qy2) - fmaxf(bx.y, qy1);
            bI = fmaxf(cw, 0.0f) * fmaxf(ch, 0.0f);
            bS = s_sa[lane] + qpa;
            bidx = lane;
        }
        if (lane < NGT - 32) {
            int n2 = lane + 32;
            float4 bx = s_box[n2];
            float cw = fminf(bx.z, qx2) - fmaxf(bx.x, qx1);
            float ch = fminf(bx.w, qy2) - fmaxf(bx.y, qy1);
            float I2 = fmaxf(cw, 0.0f) * fmaxf(ch, 0.0f);
            float S2 = s_sa[n2] + qpa;
            if (I2 * bS > bI * S2) { bI = I2; bS = S2; bidx = n2; }
        }
        #pragma unroll
        for (int off = 16; off; off >>= 1) {
            float oI = __shfl_down_sync(FULL, bI, off);
            float oS = __shfl_down_sync(FULL, bS, off);
            int   oi = __shfl_down_sync(FULL, bidx, off);
            float l = oI * bS, r = bI * oS;
            if (l > r || (l == r && oi < bidx)) { bI = oI; bS = oS; bidx = oi; }
        }
        bidx = __shfl_sync(FULL, bidx, 0);

        // class logsumexp (80 = 32 + 32 + 16); logits ~N(0,1), unshifted safe
        float s = __expf(l0) + __expf(l1);
        if (lane < 16) s += __expf(l2);
        #pragma unroll
        for (int off = 16; off; off >>= 1)
            s += __shfl_down_sync(FULL, s, off);
        s = __shfl_sync(FULL, s, 0);

        // logit[idx] from registers via shfl (no extra load)
        const int idx = (int)s_cls[bidx];
        const int sel = idx >> 5;
        float cand = (sel == 0) ? l0 : ((sel == 1) ? l1 : l2);
        const float lt = __shfl_sync(FULL, cand, idx & 31);

        if (lane == 0) {
            float4 g = s_gt[bidx];
            float d0 = u0 - g.x;
            float d1 = u1 - g.y;
            float d2 = u2 - g.z;
            float d3 = u3 - g.w;
            float dc = 5.0f * cf - 5.0f;
            loss += d0 * d0 + d1 * d1 + d2 * d2 + d3 * d3 + dc * dc
                  + __logf(s) - lt;
        }
    }

    // block reduction in double
    double v = (double)loss;
    #pragma unroll
    for (int off = 16; off; off >>= 1)
        v += __shfl_down_sync(FULL, v, off);

    if (lane == 0) s_red[wid] = v;
    __syncthreads();
    if (tid < 32) {
        v = (lane < 8) ? s_red[lane] : 0.0;
        #pragma unroll
        for (int off = 4; off; off >>= 1)
            v += __shfl_down_sync(0xffu, v, off);
    }

    // last-block-reduces (single launch, graph-replay safe)
    if (tid == 0) {
        g_part[blockIdx.x] = v;
        __threadfence();
        unsigned int done = atomicAdd(&g_flag, 1u);
        s_last = (done == NBLOCKS - 1);
    }
    __syncthreads();

    if (s_last) {
        double t = 0.0;
        for (int i = tid; i < NBLOCKS; i += BLK)
            t += g_part[i];
        #pragma unroll
        for (int off = 16; off; off >>= 1)
            t += __shfl_down_sync(FULL, t, off);
        if (lane == 0) s_red[wid] = t;
        __syncthreads();
        if (tid == 0) {
            double tot = 0.0;
            #pragma unroll
            for (int i = 0; i < 8; i++) tot += s_red[i];
            out[0] = (float)tot;
            atomicExch(&g_flag, 0u);
        }
    }
}

extern "C" void kernel_launch(void* const* d_in, const int* in_sizes, int n_in,
                              void* d_out, int out_size)
{
    const float* outp    = (const float*)d_in[0];
    const float* target  = (const float*)d_in[1];
    const float* anchors = (const float*)d_in[2];
    float* out = (float*)d_out;

    rl_loss_kernel<<<NBLOCKS, BLK>>>(outp, target, anchors, out);
}

// round 13
// speedup vs baseline: 1.3137x; 1.3137x over previous
#include <cuda_runtime.h>

// YOLOv2 region loss — R11 champion (CPT=2, 2x32 warp tiles, geometric GT
// prefilter, block queue for masked cells) + setup loads hoisted above the
// smem GT fill so the DRAM round-trip overlaps block setup.
// B=16, A=5, C=80, H=W=64, N_GT=50, STRIDE=16, THRESH=0.6

#define NA 5
#define NC 80
#define NGT 50
#define HW 4096
#define CH 85
#define BLK 256
#define NBLOCKS 640      // 327680 / 512
#define FULL 0xffffffffu

__device__ double g_part[NBLOCKS];
__device__ unsigned int g_flag;   // zero-init; last block resets each launch

__global__ __launch_bounds__(BLK, 5) void rl_loss_kernel(
    const float* __restrict__ outp,
    const float* __restrict__ target,
    const float* __restrict__ anchors,
    float* __restrict__ out)
{
    __shared__ float4 s_box[NGT];      // x1,y1,x2,y2
    __shared__ float  s_m3sa[NGT];     // -3 * gt_area  (phase-1 key)
    __shared__ float  s_sa[NGT];       // exact gt_area (phase-2)
    __shared__ float4 s_gt[NGT];       // cx,cy,w,h
    __shared__ float  s_cls[NGT];
    __shared__ double s_red[8];
    __shared__ int    s_cnt[8];
    __shared__ int    s_q[512];        // masked-cell offsets (worst case)
    __shared__ int    s_last;

    const int tid  = threadIdx.x;
    const int lane = tid & 31;
    const int wid  = tid >> 5;

    // block = 512 consecutive cells of one (b,a); warp = 2-row x 32-col tile
    const int cellblk = blockIdx.x * 512;
    const int ba      = cellblk >> 12;
    const int b       = ba / NA;
    const int a       = ba - b * NA;
    const int hwbase  = cellblk & (HW - 1);
    const int oW      = ((wid >> 1) << 7) + ((wid & 1) << 5);
    const int oA      = oW + lane;              // cell A; cell B = oA + 64

    const float* base = outp + ((size_t)ba * CH) * HW + hwbase;

    // ---- issue ALL 10 setup loads FIRST: the ~600-cycle DRAM round-trip
    // overlaps the GT smem fill + barrier below (max MLP per warp).
    float t0[2], t1[2], t2[2], t3[2], conf[2];
    #pragma unroll
    for (int c = 0; c < 2; c++) {
        const int o = oA + 64 * c;
        t0[c]   = base[o];
        t1[c]   = base[o + HW];
        t2[c]   = base[o + 2 * HW];
        t3[c]   = base[o + 3 * HW];
        conf[c] = base[o + 4 * HW];
    }

    if (tid < NGT) {
        const float* t = target + ((size_t)b * NGT + tid) * 5;
        float cls = t[0], cx = t[1], cy = t[2], gw = t[3], gh = t[4];
        float x1 = cx - gw * 0.5f, y1 = cy - gh * 0.5f;
        float x2 = cx + gw * 0.5f, y2 = cy + gh * 0.5f;
        float sa = (x2 - x1) * (y2 - y1);
        s_box[tid]  = make_float4(x1, y1, x2, y2);
        s_m3sa[tid] = -3.0f * sa;
        s_sa[tid]   = sa;
        s_gt[tid]   = make_float4(cx, cy, gw, gh);
        s_cls[tid]  = cls;
    }
    __syncthreads();

    const float aw = anchors[2 * a];
    const float ah = anchors[2 * a + 1];

    float px1[2], py1[2], px2[2], py2[2], paeps[2], mk[2];

    #pragma unroll
    for (int c = 0; c < 2; c++) {
        int hwc = hwbase + oA + 64 * c;
        int h = hwc >> 6, w = hwc & 63;
        float sx = __fdividef(1.0f, 1.0f + __expf(-t0[c]));
        float sy = __fdividef(1.0f, 1.0f + __expf(-t1[c]));
        float px = (sx + (float)w) * 16.0f;
        float py = (sy + (float)h) * 16.0f;
        float pw = __expf(t2[c]) * aw;
        float ph = __expf(t3[c]) * ah;
        px1[c] = px - pw * 0.5f;  py1[c] = py - ph * 0.5f;
        px2[c] = px + pw * 0.5f;  py2[c] = py + ph * 0.5f;
        paeps[c] = (px2[c] - px1[c]) * (py2[c] - py1[c]) + 1e-6f;
        mk[c]    = -1e30f;
    }

    // ---- Per-warp GT prefilter (necessary condition: GT box contains some
    // pred center of this warp's 512x32px strip; 1px slack >> fp error).
    unsigned f0, f1;
    {
        const float xlo = (float)(((wid & 1) << 9)) - 1.0f;
        const float xhi = xlo + 514.0f;
        const float ylo = (float)(((hwbase >> 6) + ((wid >> 1) << 1)) << 4) - 1.0f;
        const float yhi = ylo + 34.0f;
        float4 bx = s_box[lane];
        bool p = (bx.z > xlo) & (bx.x < xhi) & (bx.w > ylo) & (bx.y < yhi);
        f0 = __ballot_sync(FULL, p);
        bool q = false;
        if (lane < NGT - 32) {
            float4 b2 = s_box[lane + 32];
            q = (b2.z > xlo) & (b2.x < xhi) & (b2.w > ylo) & (b2.y < yhi);
        }
        f1 = __ballot_sync(FULL, q);
    }

    // ---- Phase 1 over surviving GTs: iou_n>0.6 <=> 8*I_n-3*Sg_n > 3*(pa+eps)
    #pragma unroll
    for (int word = 0; word < 2; word++) {
        unsigned bb = word ? f1 : f0;
        const int boff = word << 5;
        while (bb) {
            int n = (__ffs(bb) - 1) + boff;
            bb &= bb - 1;
            float4 bx = s_box[n];
            float m3  = s_m3sa[n];
            #pragma unroll
            for (int c = 0; c < 2; c++) {
                float cw = fminf(bx.z, px2[c]) - fmaxf(bx.x, px1[c]);
                float ch = fminf(bx.w, py2[c]) - fmaxf(bx.y, py1[c]);
                float I  = fmaxf(cw, 0.0f) * fmaxf(ch, 0.0f);
                mk[c] = fmaxf(mk[c], fmaf(I, 8.0f, m3));
            }
        }
    }

    float loss = 0.0f;
    const bool m0 = (mk[0] > 3.0f * paeps[0]);
    const bool m1 = (mk[1] > 3.0f * paeps[1]);
    if (!m0) loss += conf[0] * conf[0];
    if (!m1) loss += conf[1] * conf[1];

    // ---- Build deterministic block queue of masked cell offsets.
    unsigned q0 = __ballot_sync(FULL, m0);
    unsigned q1 = __ballot_sync(FULL, m1);
    if (lane == 0) s_cnt[wid] = __popc(q0) + __popc(q1);
    __syncthreads();

    int qoff = 0, qn = 0;
    #pragma unroll
    for (int i = 0; i < 8; i++) {
        int ci = s_cnt[i];
        if (i < wid) qoff += ci;
        qn += ci;
    }
    if (m0) s_q[qoff + __popc(q0 & ((1u << lane) - 1))] = oA;
    if (m1) s_q[qoff + __popc(q0) + __popc(q1 & ((1u << lane) - 1))] = oA + 64;
    __syncthreads();

    // ---- Phase 2: all warps drain the queue round-robin. Exact per-cell:
    // argmax over ALL 50 GTs (cross-mul, first-occurrence ties) + coord/conf
    // loss + class logsumexp. Class loads issued BEFORE argmax (overlap).
    for (int e = wid; e < qn; e += 8) {
        const int o = s_q[e];

        // raw logits for this cell (L1/L2 hot; broadcast loads)
        const float u0 = base[o];
        const float u1 = base[o + HW];
        const float u2 = base[o + 2 * HW];
        const float u3 = base[o + 3 * HW];
        const float cf = base[o + 4 * HW];

        // issue class loads now, consume after argmax
        const float* cl = base + o + 5 * HW;
        const float l0 = cl[(size_t)lane * HW];
        const float l1 = cl[(size_t)(lane + 32) * HW];
        const float l2 = (lane < 16) ? cl[(size_t)(lane + 64) * HW] : 0.0f;

        // rebuild pred box (uniform across warp)
        const int hwq = hwbase + o;
        const int hq = hwq >> 6, wq = hwq & 63;
        const float qsx = __fdividef(1.0f, 1.0f + __expf(-u0));
        const float qsy = __fdividef(1.0f, 1.0f + __expf(-u1));
        const float qxc = (qsx + (float)wq) * 16.0f;
        const float qyc = (qsy + (float)hq) * 16.0f;
        const float qpw = __expf(u2) * aw;
        const float qph = __expf(u3) * ah;
        const float qx1 = qxc - qpw * 0.5f, qy1 = qyc - qph * 0.5f;
        const float qx2 = qxc + qpw * 0.5f, qy2 = qyc + qph * 0.5f;
        const float qpa = (qx2 - qx1) * (qy2 - qy1) + 1e-6f;

        // lanes split 50 GTs; cross-multiplied compare (monotone-equiv to
        // iou = I/(S-I)); smaller index wins ties = first-occurrence argmax
        float bI, bS; int bidx;
        {
            float4 bx = s_box[lane];
            float cw = fminf(bx.z, qx2) - fmaxf(bx.x, qx1);
            float ch = fminf(bx.w, qy2) - fmaxf(bx.y, qy1);
            bI = fmaxf(cw, 0.0f) * fmaxf(ch, 0.0f);
            bS = s_sa[lane] + qpa;
            bidx = lane;
        }
        if (lane < NGT - 32) {
            int n2 = lane + 32;
            float4 bx = s_box[n2];
            float cw = fminf(bx.z, qx2) - fmaxf(bx.x, qx1);
            float ch = fminf(bx.w, qy2) - fmaxf(bx.y, qy1);
            float I2 = fmaxf(cw, 0.0f) * fmaxf(ch, 0.0f);
            float S2 = s_sa[n2] + qpa;
            if (I2 * bS > bI * S2) { bI = I2; bS = S2; bidx = n2; }
        }
        #pragma unroll
        for (int off = 16; off; off >>= 1) {
            float oI = __shfl_down_sync(FULL, bI, off);
            float oS = __shfl_down_sync(FULL, bS, off);
            int   oi = __shfl_down_sync(FULL, bidx, off);
            float l = oI * bS, r = bI * oS;
            if (l > r || (l == r && oi < bidx)) { bI = oI; bS = oS; bidx = oi; }
        }
        bidx = __shfl_sync(FULL, bidx, 0);

        // class logsumexp (80 = 32 + 32 + 16); logits ~N(0,1), unshifted safe
        float s = __expf(l0) + __expf(l1);
        if (lane < 16) s += __expf(l2);
        #pragma unroll
        for (int off = 16; off; off >>= 1)
            s += __shfl_down_sync(FULL, s, off);
        s = __shfl_sync(FULL, s, 0);

        // logit[idx] from registers via shfl (no extra load)
        const int idx = (int)s_cls[bidx];
        const int sel = idx >> 5;
        float cand = (sel == 0) ? l0 : ((sel == 1) ? l1 : l2);
        const float lt = __shfl_sync(FULL, cand, idx & 31);

        if (lane == 0) {
            float4 g = s_gt[bidx];
            float d0 = u0 - g.x;
            float d1 = u1 - g.y;
            float d2 = u2 - g.z;
            float d3 = u3 - g.w;
            float dc = 5.0f * cf - 5.0f;
            loss += d0 * d0 + d1 * d1 + d2 * d2 + d3 * d3 + dc * dc
                  + __logf(s) - lt;
        }
    }

    // block reduction in double
    double v = (double)loss;
    #pragma unroll
    for (int off = 16; off; off >>= 1)
        v += __shfl_down_sync(FULL, v, off);

    if (lane == 0) s_red[wid] = v;
    __syncthreads();
    if (tid < 32) {
        v = (lane < 8) ? s_red[lane] : 0.0;
        #pragma unroll
        for (int off = 4; off; off >>= 1)
            v += __shfl_down_sync(0xffu, v, off);
    }

    // last-block-reduces (single launch, graph-replay safe)
    if (tid == 0) {
        g_part[blockIdx.x] = v;
        __threadfence();
        unsigned int done = atomicAdd(&g_flag, 1u);
        s_last = (done == NBLOCKS - 1);
    }
    __syncthreads();

    if (s_last) {
        double t = 0.0;
        for (int i = tid; i < NBLOCKS; i += BLK)
            t += g_part[i];
        #pragma unroll
        for (int off = 16; off; off >>= 1)
            t += __shfl_down_sync(FULL, t, off);
        if (lane == 0) s_red[wid] = t;
        __syncthreads();
        if (tid == 0) {
            double tot = 0.0;
            #pragma unroll
            for (int i = 0; i < 8; i++) tot += s_red[i];
            out[0] = (float)tot;
            atomicExch(&g_flag, 0u);
        }
    }
}

extern "C" void kernel_launch(void* const* d_in, const int* in_sizes, int n_in,
                              void* d_out, int out_size)
{
    const float* outp    = (const float*)d_in[0];
    const float* target  = (const float*)d_in[1];
    const float* anchors = (const float*)d_in[2];
    float* out = (float*)d_out;

    rl_loss_kernel<<<NBLOCKS, BLK>>>(outp, target, anchors, out);
}

// round 14
// speedup vs baseline: 1.3170x; 1.0025x over previous
#include <cuda_runtime.h>

// YOLOv2 region loss — R13 (CPT=2, hoisted setup loads, geometric GT
// prefilter, block queue) + half-warp-paired phase 2: each warp round
// processes TWO masked cells (16 lanes each) to halve heavy-block tails.
// B=16, A=5, C=80, H=W=64, N_GT=50, STRIDE=16, THRESH=0.6

#define NA 5
#define NC 80
#define NGT 50
#define HW 4096
#define CH 85
#define BLK 256
#define NBLOCKS 640      // 327680 / 512
#define FULL 0xffffffffu

__device__ double g_part[NBLOCKS];
__device__ unsigned int g_flag;   // zero-init; last block resets each launch

__global__ __launch_bounds__(BLK, 5) void rl_loss_kernel(
    const float* __restrict__ outp,
    const float* __restrict__ target,
    const float* __restrict__ anchors,
    float* __restrict__ out)
{
    __shared__ float4 s_box[NGT];      // x1,y1,x2,y2
    __shared__ float  s_m3sa[NGT];     // -3 * gt_area  (phase-1 key)
    __shared__ float  s_sa[NGT];       // exact gt_area (phase-2)
    __shared__ float4 s_gt[NGT];       // cx,cy,w,h
    __shared__ float  s_cls[NGT];
    __shared__ double s_red[8];
    __shared__ int    s_cnt[8];
    __shared__ int    s_q[512];        // masked-cell offsets (worst case)
    __shared__ int    s_last;

    const int tid  = threadIdx.x;
    const int lane = tid & 31;
    const int wid  = tid >> 5;

    // block = 512 consecutive cells of one (b,a); warp = 2-row x 32-col tile
    const int cellblk = blockIdx.x * 512;
    const int ba      = cellblk >> 12;
    const int b       = ba / NA;
    const int a       = ba - b * NA;
    const int hwbase  = cellblk & (HW - 1);
    const int oW      = ((wid >> 1) << 7) + ((wid & 1) << 5);
    const int oA      = oW + lane;              // cell A; cell B = oA + 64

    const float* base = outp + ((size_t)ba * CH) * HW + hwbase;

    // ---- issue ALL 10 setup loads FIRST: the DRAM round-trip overlaps the
    // GT smem fill + barrier below.
    float t0[2], t1[2], t2[2], t3[2], conf[2];
    #pragma unroll
    for (int c = 0; c < 2; c++) {
        const int o = oA + 64 * c;
        t0[c]   = base[o];
        t1[c]   = base[o + HW];
        t2[c]   = base[o + 2 * HW];
        t3[c]   = base[o + 3 * HW];
        conf[c] = base[o + 4 * HW];
    }

    if (tid < NGT) {
        const float* t = target + ((size_t)b * NGT + tid) * 5;
        float cls = t[0], cx = t[1], cy = t[2], gw = t[3], gh = t[4];
        float x1 = cx - gw * 0.5f, y1 = cy - gh * 0.5f;
        float x2 = cx + gw * 0.5f, y2 = cy + gh * 0.5f;
        float sa = (x2 - x1) * (y2 - y1);
        s_box[tid]  = make_float4(x1, y1, x2, y2);
        s_m3sa[tid] = -3.0f * sa;
        s_sa[tid]   = sa;
        s_gt[tid]   = make_float4(cx, cy, gw, gh);
        s_cls[tid]  = cls;
    }
    __syncthreads();

    const float aw = anchors[2 * a];
    const float ah = anchors[2 * a + 1];

    float px1[2], py1[2], px2[2], py2[2], paeps[2], mk[2];

    #pragma unroll
    for (int c = 0; c < 2; c++) {
        int hwc = hwbase + oA + 64 * c;
        int h = hwc >> 6, w = hwc & 63;
        float sx = __fdividef(1.0f, 1.0f + __expf(-t0[c]));
        float sy = __fdividef(1.0f, 1.0f + __expf(-t1[c]));
        float px = (sx + (float)w) * 16.0f;
        float py = (sy + (float)h) * 16.0f;
        float pw = __expf(t2[c]) * aw;
        float ph = __expf(t3[c]) * ah;
        px1[c] = px - pw * 0.5f;  py1[c] = py - ph * 0.5f;
        px2[c] = px + pw * 0.5f;  py2[c] = py + ph * 0.5f;
        paeps[c] = (px2[c] - px1[c]) * (py2[c] - py1[c]) + 1e-6f;
        mk[c]    = -1e30f;
    }

    // ---- Per-warp GT prefilter (necessary condition: GT box contains some
    // pred center of this warp's 512x32px strip; 1px slack >> fp error).
    unsigned f0, f1;
    {
        const float xlo = (float)(((wid & 1) << 9)) - 1.0f;
        const float xhi = xlo + 514.0f;
        const float ylo = (float)(((hwbase >> 6) + ((wid >> 1) << 1)) << 4) - 1.0f;
        const float yhi = ylo + 34.0f;
        float4 bx = s_box[lane];
        bool p = (bx.z > xlo) & (bx.x < xhi) & (bx.w > ylo) & (bx.y < yhi);
        f0 = __ballot_sync(FULL, p);
        bool q = false;
        if (lane < NGT - 32) {
            float4 b2 = s_box[lane + 32];
            q = (b2.z > xlo) & (b2.x < xhi) & (b2.w > ylo) & (b2.y < yhi);
        }
        f1 = __ballot_sync(FULL, q);
    }

    // ---- Phase 1 over surviving GTs: iou_n>0.6 <=> 8*I_n-3*Sg_n > 3*(pa+eps)
    #pragma unroll
    for (int word = 0; word < 2; word++) {
        unsigned bb = word ? f1 : f0;
        const int boff = word << 5;
        while (bb) {
            int n = (__ffs(bb) - 1) + boff;
            bb &= bb - 1;
            float4 bx = s_box[n];
            float m3  = s_m3sa[n];
            #pragma unroll
            for (int c = 0; c < 2; c++) {
                float cw = fminf(bx.z, px2[c]) - fmaxf(bx.x, px1[c]);
                float ch = fminf(bx.w, py2[c]) - fmaxf(bx.y, py1[c]);
                float I  = fmaxf(cw, 0.0f) * fmaxf(ch, 0.0f);
                mk[c] = fmaxf(mk[c], fmaf(I, 8.0f, m3));
            }
        }
    }

    float loss = 0.0f;
    const bool m0 = (mk[0] > 3.0f * paeps[0]);
    const bool m1 = (mk[1] > 3.0f * paeps[1]);
    if (!m0) loss += conf[0] * conf[0];
    if (!m1) loss += conf[1] * conf[1];

    // ---- Build deterministic block queue of masked cell offsets.
    unsigned q0 = __ballot_sync(FULL, m0);
    unsigned q1 = __ballot_sync(FULL, m1);
    if (lane == 0) s_cnt[wid] = __popc(q0) + __popc(q1);
    __syncthreads();

    int qoff = 0, qn = 0;
    #pragma unroll
    for (int i = 0; i < 8; i++) {
        int ci = s_cnt[i];
        if (i < wid) qoff += ci;
        qn += ci;
    }
    if (m0) s_q[qoff + __popc(q0 & ((1u << lane) - 1))] = oA;
    if (m1) s_q[qoff + __popc(q0) + __popc(q1 & ((1u << lane) - 1))] = oA + 64;
    __syncthreads();

    // ---- Phase 2: warps drain the queue in PAIRS — half-warp (16 lanes)
    // per masked cell. Exact per-cell: argmax over ALL 50 GTs (cross-mul,
    // first-occurrence ties) + coord/conf loss + class logsumexp.
    // Odd tail: half 1 re-processes a dummy entry, contribution discarded
    // (uniform control flow — all width-16 shfls with full mask are safe).
    for (int e0 = (wid << 1); e0 < qn; e0 += 16) {
        const int half = lane >> 4;            // 0 or 1
        const int l16  = lane & 15;
        const int eh   = e0 + half;
        const bool val = (eh < qn);
        const int o = s_q[val ? eh : e0];

        // raw logits for this cell (broadcast within the half; L1/L2 hot)
        const float u0 = base[o];
        const float u1 = base[o + HW];
        const float u2 = base[o + 2 * HW];
        const float u3 = base[o + 3 * HW];
        const float cf = base[o + 4 * HW];

        // issue class loads now, consume after argmax (80 = 16 lanes x 5)
        const float* cl = base + o + 5 * HW;
        float lv0 = cl[(size_t)(l16     ) * HW];
        float lv1 = cl[(size_t)(l16 + 16) * HW];
        float lv2 = cl[(size_t)(l16 + 32) * HW];
        float lv3 = cl[(size_t)(l16 + 48) * HW];
        float lv4 = cl[(size_t)(l16 + 64) * HW];

        // rebuild pred box (uniform within the half)
        const int hwq = hwbase + o;
        const int hq = hwq >> 6, wq = hwq & 63;
        const float qsx = __fdividef(1.0f, 1.0f + __expf(-u0));
        const float qsy = __fdividef(1.0f, 1.0f + __expf(-u1));
        const float qxc = (qsx + (float)wq) * 16.0f;
        const float qyc = (qsy + (float)hq) * 16.0f;
        const float qpw = __expf(u2) * aw;
        const float qph = __expf(u3) * ah;
        const float qx1 = qxc - qpw * 0.5f, qy1 = qyc - qph * 0.5f;
        const float qx2 = qxc + qpw * 0.5f, qy2 = qyc + qph * 0.5f;
        const float qpa = (qx2 - qx1) * (qy2 - qy1) + 1e-6f;

        // 16 lanes split 50 GTs (n = l16 + 16k); cross-multiplied compare
        // (monotone-equiv to iou = I/(S-I)); increasing-n order with strict >
        // per lane + smaller-index cross-lane tie-break = first-occurrence.
        float bI = -1.0f, bS = 1.0f;
        int bidx = 0;
        #pragma unroll
        for (int k = 0; k < 4; k++) {
            int n = l16 + (k << 4);
            if (n < NGT) {
                float4 bx = s_box[n];
                float cw = fminf(bx.z, qx2) - fmaxf(bx.x, qx1);
                float ch = fminf(bx.w, qy2) - fmaxf(bx.y, qy1);
                float I  = fmaxf(cw, 0.0f) * fmaxf(ch, 0.0f);
                float S  = s_sa[n] + qpa;
                if (I * bS > bI * S) { bI = I; bS = S; bidx = n; }
            }
        }
        #pragma unroll
        for (int off = 8; off; off >>= 1) {
            float oI = __shfl_down_sync(FULL, bI, off, 16);
            float oS = __shfl_down_sync(FULL, bS, off, 16);
            int   oi = __shfl_down_sync(FULL, bidx, off, 16);
            float l = oI * bS, r = bI * oS;
            if (l > r || (l == r && oi < bidx)) { bI = oI; bS = oS; bidx = oi; }
        }
        bidx = __shfl_sync(FULL, bidx, 0, 16);

        // class logsumexp (logits ~N(0,1): unshifted is safe)
        float s = __expf(lv0) + __expf(lv1) + __expf(lv2)
                + __expf(lv3) + __expf(lv4);
        #pragma unroll
        for (int off = 8; off; off >>= 1)
            s += __shfl_down_sync(FULL, s, off, 16);
        s = __shfl_sync(FULL, s, 0, 16);

        // logit[idx] from registers via width-16 shfl (no extra load)
        const int idx  = (int)s_cls[bidx];
        const int slot = idx >> 4;
        float cand = (slot == 0) ? lv0 : (slot == 1) ? lv1
                   : (slot == 2) ? lv2 : (slot == 3) ? lv3 : lv4;
        const float lt = __shfl_sync(FULL, cand, idx & 15, 16);

        if (l16 == 0 && val) {
            float4 g = s_gt[bidx];
            float d0 = u0 - g.x;
            float d1 = u1 - g.y;
            float d2 = u2 - g.z;
            float d3 = u3 - g.w;
            float dc = 5.0f * cf - 5.0f;
            loss += d0 * d0 + d1 * d1 + d2 * d2 + d3 * d3 + dc * dc
                  + __logf(s) - lt;
        }
    }

    // block reduction in double
    double v = (double)loss;
    #pragma unroll
    for (int off = 16; off; off >>= 1)
        v += __shfl_down_sync(FULL, v, off);

    if (lane == 0) s_red[wid] = v;
    __syncthreads();
    if (tid < 32) {
        v = (lane < 8) ? s_red[lane] : 0.0;
        #pragma unroll
        for (int off = 4; off; off >>= 1)
            v += __shfl_down_sync(0xffu, v, off);
    }

    // last-block-reduces (single launch, graph-replay safe)
    if (tid == 0) {
        g_part[blockIdx.x] = v;
        __threadfence();
        unsigned int done = atomicAdd(&g_flag, 1u);
        s_last = (done == NBLOCKS - 1);
    }
    __syncthreads();

    if (s_last) {
        double t = 0.0;
        for (int i = tid; i < NBLOCKS; i += BLK)
            t += g_part[i];
        #pragma unroll
        for (int off = 16; off; off >>= 1)
            t += __shfl_down_sync(FULL, t, off);
        if (lane == 0) s_red[wid] = t;
        __syncthreads();
        if (tid == 0) {
            double tot = 0.0;
            #pragma unroll
            for (int i = 0; i < 8; i++) tot += s_red[i];
            out[0] = (float)tot;
            atomicExch(&g_flag, 0u);
        }
    }
}

extern "C" void kernel_launch(void* const* d_in, const int* in_sizes, int n_in,
                              void* d_out, int out_size)
{
    const float* outp    = (const float*)d_in[0];
    const float* target  = (const float*)d_in[1];
    const float* anchors = (const float*)d_in[2];
    float* out = (float*)d_out;

    rl_loss_kernel<<<NBLOCKS, BLK>>>(outp, target, anchors, out);
}